// round 12
// baseline (speedup 1.0000x reference)
#include <cuda_runtime.h>
#include <cuda_fp16.h>

#define DD 160
#define HH 192
#define WW 224
#define VV (DD*HH*WW)        // 6881280
#define W4 (WW/4)            // 56 float4 per input row
#define WU2 (WW/4)           // 56 uint2 (4-half) per row
#define VU2 (VV/4)           // uint2 elems per field = 1720320
#define PL2 (HH*WW/4)        // uint2 per d-plane = 10752

#define WC 56                // W outputs per block
#define HC 32                // H outputs per block
#define RH 40                // raw rows (HC + 8)
#define RST 68               // raw smem stride (uints = half2 voxels)
#define SST 15               // summed smem stride (uint2 per row)

#define DCHUNK 10            // dpass D outputs per block (160/10 = 16 chunks)

// fp16 scratch: 5 fields x VV halves (68.8 MB) — WH-summed fields
__device__ __half g_B[5u * VV];

union U2H4 { uint2 u; __half2 h[2]; };
union U4H2 { uint4 u; __half2 h[4]; };

// ---------------------------------------------------------------------------
// Fused pass 1+2 (CHAMPION, unchanged): W-sum then H-sum, fp32 in, fp16 out.
// Raw tile held as packed half2(I,J) -> 34.9 KB smem -> 6 blocks/SM.
// ---------------------------------------------------------------------------
__global__ void __launch_bounds__(256) whpass(const float* __restrict__ I,
                                              const float* __restrict__ J,
                                              float* __restrict__ out) {
    __shared__ __align__(16) unsigned sR[RH * RST];  // 10.9 KB: half2(I,J)/voxel
    __shared__ __align__(16) uint2 sS[5 * RH * SST]; // 24 KB

    const int tid = threadIdx.x;
    const int w0  = blockIdx.x * WC;
    const int h0  = blockIdx.y * HC;
    const int d   = blockIdx.z;
    if (blockIdx.x == 0 && blockIdx.y == 0 && blockIdx.z == 0 && tid == 0)
        out[0] = 0.f;

    // ---- phase 0: load raw I,J tile rows [h0-4, h0+36), w [w0-4, w0+60) ----
    const int fb = (w0 - 4) >> 2;           // first float4 index (may be -1)
    const float4* I4 = (const float4*)I;
    const float4* J4 = (const float4*)J;
    for (int i = tid; i < RH * 16; i += 256) {
        const int r = i >> 4, c = i & 15;
        const int gh = h0 - 4 + r;
        const int gf = fb + c;
        float4 a = make_float4(0.f, 0.f, 0.f, 0.f);
        float4 b = a;
        if (gh >= 0 && gh < HH && gf >= 0 && gf < W4) {
            const size_t q = ((size_t)d * HH + gh) * W4 + gf;
            a = I4[q]; b = J4[q];
        }
        U4H2 t;
        t.h[0] = __floats2half2_rn(a.x, b.x);
        t.h[1] = __floats2half2_rn(a.y, b.y);
        t.h[2] = __floats2half2_rn(a.z, b.z);
        t.h[3] = __floats2half2_rn(a.w, b.w);
        *(uint4*)&sR[r * RST + 4 * c] = t.u;    // 16B aligned
    }
    __syncthreads();

    // ---- phase 1: W-sums (sliding 9-tap), 4 outputs/item, 5 fields -> sS ----
    for (int i = tid; i < 14 * RH; i += 256) {
        const int g = i / RH;              // output float4-group 0..13
        const int r = i - g * RH;          // row 0..39 (consecutive tids -> r)
        const int base = r * RST + 4 * g;  // 16B aligned

        float iv[12], jv[12];
        U4H2 q0, q1, q2;
        q0.u = *(const uint4*)&sR[base];
        q1.u = *(const uint4*)&sR[base + 4];
        q2.u = *(const uint4*)&sR[base + 8];
#pragma unroll
        for (int t = 0; t < 4; t++) {
            float2 v0 = __half22float2(q0.h[t]);
            float2 v1 = __half22float2(q1.h[t]);
            float2 v2 = __half22float2(q2.h[t]);
            iv[t] = v0.x;     jv[t] = v0.y;
            iv[t + 4] = v1.x; jv[t + 4] = v1.y;
            iv[t + 8] = v2.x; jv[t + 8] = v2.y;
        }

        float oi[4], oj[4], oi2[4], oj2[4], oij[4];
        float si=0.f, sj=0.f, si2=0.f, sj2=0.f, sij=0.f;
#pragma unroll
        for (int t = 0; t < 9; t++) {
            float x = iv[t], y = jv[t];
            si += x; sj += y; si2 += x*x; sj2 += y*y; sij += x*y;
        }
        oi[0]=si; oj[0]=sj; oi2[0]=si2; oj2[0]=sj2; oij[0]=sij;
#pragma unroll
        for (int k = 1; k < 4; k++) {
            float ia = iv[k+8], ir = iv[k-1];
            float ja = jv[k+8], jr = jv[k-1];
            si  += ia - ir;        sj  += ja - jr;
            si2 += ia*ia - ir*ir;  sj2 += ja*ja - jr*jr;
            sij += ia*ja - ir*jr;
            oi[k]=si; oj[k]=sj; oi2[k]=si2; oj2[k]=sj2; oij[k]=sij;
        }

        const int so = r * SST + g;
        U2H4 t0, t1, t2, t3, t4;
        t0.h[0]=__floats2half2_rn(oi[0],oi[1]);   t0.h[1]=__floats2half2_rn(oi[2],oi[3]);
        t1.h[0]=__floats2half2_rn(oj[0],oj[1]);   t1.h[1]=__floats2half2_rn(oj[2],oj[3]);
        t2.h[0]=__floats2half2_rn(oi2[0],oi2[1]); t2.h[1]=__floats2half2_rn(oi2[2],oi2[3]);
        t3.h[0]=__floats2half2_rn(oj2[0],oj2[1]); t3.h[1]=__floats2half2_rn(oj2[2],oj2[3]);
        t4.h[0]=__floats2half2_rn(oij[0],oij[1]); t4.h[1]=__floats2half2_rn(oij[2],oij[3]);
        sS[0*RH*SST + so] = t0.u;
        sS[1*RH*SST + so] = t1.u;
        sS[2*RH*SST + so] = t2.u;
        sS[3*RH*SST + so] = t3.u;
        sS[4*RH*SST + so] = t4.u;
    }
    __syncthreads();

    // ---- phase 2: H-sums (running window over sS rows) -> g_B --------------
    if (tid < 224) {
        const int col  = tid % 14;          // uint2 column in tile
        const int rest = tid / 14;          // 0..15
        const int seg  = rest & 7;          // 4-row segment
        const int grp  = rest >> 3;         // 0: fields 0-2, 1: fields 3-4
        const int f0 = grp ? 3 : 0;
        const int f1 = grp ? 5 : 3;
        const int o0 = seg * 4;             // local output row base

        uint2* Bg = (uint2*)g_B;
        for (int f = f0; f < f1; f++) {
            const uint2* sf = &sS[f * RH * SST];
            __half2 s0 = __float2half2_rn(0.f), s1 = s0;
#pragma unroll
            for (int t = 0; t < 9; t++) {        // taps lr = o0 .. o0+8
                U2H4 v; v.u = sf[(o0 + t) * SST + col];
                s0 = __hadd2(s0, v.h[0]); s1 = __hadd2(s1, v.h[1]);
            }
            const size_t fbase = (size_t)f * VU2 + blockIdx.x * 14 + col;
#pragma unroll
            for (int k = 0; k < 4; k++) {
                U2H4 o; o.h[0] = s0; o.h[1] = s1;
                Bg[fbase + ((size_t)d * HH + h0 + o0 + k) * WU2] = o.u;
                if (k < 3) {
                    U2H4 va, vs;
                    va.u = sf[(o0 + k + 9) * SST + col];
                    vs.u = sf[(o0 + k) * SST + col];
                    s0 = __hadd2(__hsub2(s0, vs.h[0]), va.h[0]);
                    s1 = __hadd2(__hsub2(s1, vs.h[1]), va.h[1]);
                }
            }
        }
    }
}

// ---------------------------------------------------------------------------
// Pass 3: along D. Chunk 10, 2-plane batched loads, regs capped at 64 so
// 4 blocks/SM are resident (672 blocks = 4.54/SM).
// ---------------------------------------------------------------------------
__device__ __forceinline__ float cc1(float si, float sj, float si2, float sj2, float sij) {
    const float inv = 1.0f / 729.0f;
    float cross = sij - si * sj * inv;
    float ivar  = si2 - si * si * inv;
    float jvar  = sj2 - sj * sj * inv;
    return __fdividef(cross * cross, ivar * jvar + 1e-5f);
}

__global__ void __launch_bounds__(256, 4) dpass(float* __restrict__ out) {
    const int tid = threadIdx.x;
    const int col = blockIdx.x * 256 + tid;      // uint2 index within plane
    const int d0  = blockIdx.y * DCHUNK;
    const uint2* B = (const uint2*)g_B;

    __half2 z2 = __float2half2_rn(0.f);
    __half2 aI0=z2, aI1=z2, aJ0=z2, aJ1=z2, aI20=z2, aI21=z2,
            aJ20=z2, aJ21=z2, aIJ0=z2, aIJ1=z2;

#define LOADTAP(dst, cond, dp) { \
    if (cond) { const unsigned q_ = (unsigned)(dp) * PL2 + col; \
        dst[0].u = B[0u*VU2 + q_]; dst[1].u = B[1u*VU2 + q_]; \
        dst[2].u = B[2u*VU2 + q_]; dst[3].u = B[3u*VU2 + q_]; \
        dst[4].u = B[4u*VU2 + q_]; } \
    else { uint2 z = make_uint2(0u, 0u); \
        dst[0].u = z; dst[1].u = z; dst[2].u = z; dst[3].u = z; dst[4].u = z; } }

#define APPLY(v, HOP) { \
    aI0  = HOP(aI0,  v[0].h[0]); aI1  = HOP(aI1,  v[0].h[1]); \
    aJ0  = HOP(aJ0,  v[1].h[0]); aJ1  = HOP(aJ1,  v[1].h[1]); \
    aI20 = HOP(aI20, v[2].h[0]); aI21 = HOP(aI21, v[2].h[1]); \
    aJ20 = HOP(aJ20, v[3].h[0]); aJ21 = HOP(aJ21, v[3].h[1]); \
    aIJ0 = HOP(aIJ0, v[4].h[0]); aIJ1 = HOP(aIJ1, v[4].h[1]); }

#define CCEMIT { \
    float2 fI0=__half22float2(aI0),  fI1=__half22float2(aI1); \
    float2 fJ0=__half22float2(aJ0),  fJ1=__half22float2(aJ1); \
    float2 fA0=__half22float2(aI20), fA1=__half22float2(aI21); \
    float2 fB0=__half22float2(aJ20), fB1=__half22float2(aJ21); \
    float2 fC0=__half22float2(aIJ0), fC1=__half22float2(aIJ1); \
    acc += cc1(fI0.x, fJ0.x, fA0.x, fB0.x, fC0.x); \
    acc += cc1(fI0.y, fJ0.y, fA0.y, fB0.y, fC0.y); \
    acc += cc1(fI1.x, fJ1.x, fA1.x, fB1.x, fC1.x); \
    acc += cc1(fI1.y, fJ1.y, fA1.y, fB1.y, fC1.y); }

    // prologue: window for plane d0 (taps d0-4 .. d0+4)
#pragma unroll
    for (int t = -4; t <= 4; t++) {
        int dt = d0 + t;                          // d0+4 <= 154 < 160 always
        if (dt >= 0) {
            U2H4 v[5];
            LOADTAP(v, true, dt);
            APPLY(v, __hadd2);
        }
    }

    float acc = 0.f;
#pragma unroll 5
    for (int dd = 0; dd < DCHUNK; dd += 2) {
        const int d = d0 + dd;
        U2H4 va[5], vs[5], wa[5], ws[5];
        LOADTAP(va, (d + 5) < DD, d + 5);
        LOADTAP(vs, (d - 4) >= 0, d - 4);
        LOADTAP(wa, (d + 6) < DD, d + 6);
        LOADTAP(ws, (d - 3) >= 0, d - 3);
        CCEMIT;                       // plane d
        APPLY(va, __hadd2);
        APPLY(vs, __hsub2);
        CCEMIT;                       // plane d+1
        APPLY(wa, __hadd2);
        APPLY(ws, __hsub2);
    }
#undef LOADTAP
#undef APPLY
#undef CCEMIT

    // block reduction
#pragma unroll
    for (int o = 16; o > 0; o >>= 1) acc += __shfl_xor_sync(0xFFFFFFFFu, acc, o);
    __shared__ float wsum[8];
    if ((tid & 31) == 0) wsum[tid >> 5] = acc;
    __syncthreads();
    if (tid == 0) {
        float s = 0.f;
#pragma unroll
        for (int i = 0; i < 8; i++) s += wsum[i];
        atomicAdd(out, -s * (1.0f / (float)VV));
    }
}

// ---------------------------------------------------------------------------
extern "C" void kernel_launch(void* const* d_in, const int* in_sizes, int n_in,
                              void* d_out, int out_size) {
    const float* I = (const float*)d_in[0];
    const float* J = (const float*)d_in[1];
    float* out = (float*)d_out;

    whpass<<<dim3(4, 6, DD), 256>>>(I, J, out);  // 4 W x 6 H x 160 d
    dpass<<<dim3(42, 16), 256>>>(out);           // 10752 u2-cols / 256, 16 D-chunks
}

// round 13
// speedup vs baseline: 1.2281x; 1.2281x over previous
#include <cuda_runtime.h>
#include <cuda_fp16.h>

#define DD 160
#define HH 192
#define WW 224
#define VV (DD*HH*WW)        // 6881280
#define W4 (WW/4)            // 56 float4 per input row
#define WU2 (WW/4)           // 56 uint2 (4-half) per row
#define VU2 (VV/4)           // uint2 elems per field = 1720320
#define VH2 (VV/2)           // half2 elems per field = 3440640
#define PLH (HH*WW/2)        // half2 per d-plane = 21504

#define WC 56                // W outputs per block
#define HC 32                // H outputs per block
#define RH 40                // raw rows (HC + 8)
#define RST 68               // raw smem stride (uints = half2 voxels)
#define SST 15               // summed smem stride (uint2 per row)

// fp16 scratch: 5 fields x VV halves (68.8 MB) — WH-summed fields
__device__ __half g_B[5u * VV];

union U2H4 { uint2 u; __half2 h[2]; };
union U4H2 { uint4 u; __half2 h[4]; };

// ---------------------------------------------------------------------------
// Fused pass 1+2 (CHAMPION, unchanged): W-sum then H-sum, fp32 in, fp16 out.
// Raw tile held as packed half2(I,J) -> 34.9 KB smem -> 6 blocks/SM.
// ---------------------------------------------------------------------------
__global__ void __launch_bounds__(256) whpass(const float* __restrict__ I,
                                              const float* __restrict__ J,
                                              float* __restrict__ out) {
    __shared__ __align__(16) unsigned sR[RH * RST];  // 10.9 KB: half2(I,J)/voxel
    __shared__ __align__(16) uint2 sS[5 * RH * SST]; // 24 KB

    const int tid = threadIdx.x;
    const int w0  = blockIdx.x * WC;
    const int h0  = blockIdx.y * HC;
    const int d   = blockIdx.z;
    if (blockIdx.x == 0 && blockIdx.y == 0 && blockIdx.z == 0 && tid == 0)
        out[0] = 0.f;

    // ---- phase 0: load raw I,J tile rows [h0-4, h0+36), w [w0-4, w0+60) ----
    const int fb = (w0 - 4) >> 2;           // first float4 index (may be -1)
    const float4* I4 = (const float4*)I;
    const float4* J4 = (const float4*)J;
    for (int i = tid; i < RH * 16; i += 256) {
        const int r = i >> 4, c = i & 15;
        const int gh = h0 - 4 + r;
        const int gf = fb + c;
        float4 a = make_float4(0.f, 0.f, 0.f, 0.f);
        float4 b = a;
        if (gh >= 0 && gh < HH && gf >= 0 && gf < W4) {
            const size_t q = ((size_t)d * HH + gh) * W4 + gf;
            a = I4[q]; b = J4[q];
        }
        U4H2 t;
        t.h[0] = __floats2half2_rn(a.x, b.x);
        t.h[1] = __floats2half2_rn(a.y, b.y);
        t.h[2] = __floats2half2_rn(a.z, b.z);
        t.h[3] = __floats2half2_rn(a.w, b.w);
        *(uint4*)&sR[r * RST + 4 * c] = t.u;    // 16B aligned
    }
    __syncthreads();

    // ---- phase 1: W-sums (sliding 9-tap), 4 outputs/item, 5 fields -> sS ----
    for (int i = tid; i < 14 * RH; i += 256) {
        const int g = i / RH;              // output float4-group 0..13
        const int r = i - g * RH;          // row 0..39 (consecutive tids -> r)
        const int base = r * RST + 4 * g;  // 16B aligned

        float iv[12], jv[12];
        U4H2 q0, q1, q2;
        q0.u = *(const uint4*)&sR[base];
        q1.u = *(const uint4*)&sR[base + 4];
        q2.u = *(const uint4*)&sR[base + 8];
#pragma unroll
        for (int t = 0; t < 4; t++) {
            float2 v0 = __half22float2(q0.h[t]);
            float2 v1 = __half22float2(q1.h[t]);
            float2 v2 = __half22float2(q2.h[t]);
            iv[t] = v0.x;     jv[t] = v0.y;
            iv[t + 4] = v1.x; jv[t + 4] = v1.y;
            iv[t + 8] = v2.x; jv[t + 8] = v2.y;
        }

        float oi[4], oj[4], oi2[4], oj2[4], oij[4];
        float si=0.f, sj=0.f, si2=0.f, sj2=0.f, sij=0.f;
#pragma unroll
        for (int t = 0; t < 9; t++) {
            float x = iv[t], y = jv[t];
            si += x; sj += y; si2 += x*x; sj2 += y*y; sij += x*y;
        }
        oi[0]=si; oj[0]=sj; oi2[0]=si2; oj2[0]=sj2; oij[0]=sij;
#pragma unroll
        for (int k = 1; k < 4; k++) {
            float ia = iv[k+8], ir = iv[k-1];
            float ja = jv[k+8], jr = jv[k-1];
            si  += ia - ir;        sj  += ja - jr;
            si2 += ia*ia - ir*ir;  sj2 += ja*ja - jr*jr;
            sij += ia*ja - ir*jr;
            oi[k]=si; oj[k]=sj; oi2[k]=si2; oj2[k]=sj2; oij[k]=sij;
        }

        const int so = r * SST + g;
        U2H4 t0, t1, t2, t3, t4;
        t0.h[0]=__floats2half2_rn(oi[0],oi[1]);   t0.h[1]=__floats2half2_rn(oi[2],oi[3]);
        t1.h[0]=__floats2half2_rn(oj[0],oj[1]);   t1.h[1]=__floats2half2_rn(oj[2],oj[3]);
        t2.h[0]=__floats2half2_rn(oi2[0],oi2[1]); t2.h[1]=__floats2half2_rn(oi2[2],oi2[3]);
        t3.h[0]=__floats2half2_rn(oj2[0],oj2[1]); t3.h[1]=__floats2half2_rn(oj2[2],oj2[3]);
        t4.h[0]=__floats2half2_rn(oij[0],oij[1]); t4.h[1]=__floats2half2_rn(oij[2],oij[3]);
        sS[0*RH*SST + so] = t0.u;
        sS[1*RH*SST + so] = t1.u;
        sS[2*RH*SST + so] = t2.u;
        sS[3*RH*SST + so] = t3.u;
        sS[4*RH*SST + so] = t4.u;
    }
    __syncthreads();

    // ---- phase 2: H-sums (running window over sS rows) -> g_B --------------
    if (tid < 224) {
        const int col  = tid % 14;          // uint2 column in tile
        const int rest = tid / 14;          // 0..15
        const int seg  = rest & 7;          // 4-row segment
        const int grp  = rest >> 3;         // 0: fields 0-2, 1: fields 3-4
        const int f0 = grp ? 3 : 0;
        const int f1 = grp ? 5 : 3;
        const int o0 = seg * 4;             // local output row base

        uint2* Bg = (uint2*)g_B;
        for (int f = f0; f < f1; f++) {
            const uint2* sf = &sS[f * RH * SST];
            __half2 s0 = __float2half2_rn(0.f), s1 = s0;
#pragma unroll
            for (int t = 0; t < 9; t++) {        // taps lr = o0 .. o0+8
                U2H4 v; v.u = sf[(o0 + t) * SST + col];
                s0 = __hadd2(s0, v.h[0]); s1 = __hadd2(s1, v.h[1]);
            }
            const size_t fbase = (size_t)f * VU2 + blockIdx.x * 14 + col;
#pragma unroll
            for (int k = 0; k < 4; k++) {
                U2H4 o; o.h[0] = s0; o.h[1] = s1;
                Bg[fbase + ((size_t)d * HH + h0 + o0 + k) * WU2] = o.u;
                if (k < 3) {
                    U2H4 va, vs;
                    va.u = sf[(o0 + k + 9) * SST + col];
                    vs.u = sf[(o0 + k) * SST + col];
                    s0 = __hadd2(__hsub2(s0, vs.h[0]), va.h[0]);
                    s1 = __hadd2(__hsub2(s1, vs.h[1]), va.h[1]);
                }
            }
        }
    }
}

// ---------------------------------------------------------------------------
// Pass 3: along D. half2-granularity threads (21504 cols), chunk 16,
// 2-plane batched loads (20 LDG.32 in flight). 840 blocks, no reg cap.
// ---------------------------------------------------------------------------
__device__ __forceinline__ float cc1(float si, float sj, float si2, float sj2, float sij) {
    const float inv = 1.0f / 729.0f;
    float cross = sij - si * sj * inv;
    float ivar  = si2 - si * si * inv;
    float jvar  = sj2 - sj * sj * inv;
    return __fdividef(cross * cross, ivar * jvar + 1e-5f);
}

__global__ void __launch_bounds__(256) dpass(float* __restrict__ out) {
    const int tid = threadIdx.x;
    const int col = blockIdx.x * 256 + tid;      // half2 index within plane
    const int d0  = blockIdx.y * 16;
    const __half2* B = (const __half2*)g_B;

    const __half2 z2 = __float2half2_rn(0.f);
    __half2 aI=z2, aJ=z2, aI2=z2, aJ2=z2, aIJ=z2;

#define LOADTAP(dst, cond, dp) { \
    if (cond) { const unsigned q_ = (unsigned)(dp) * PLH + col; \
        dst[0] = B[q_];            dst[1] = B[VH2 + q_]; \
        dst[2] = B[2u*VH2 + q_];   dst[3] = B[3u*VH2 + q_]; \
        dst[4] = B[4u*VH2 + q_]; } \
    else { dst[0]=z2; dst[1]=z2; dst[2]=z2; dst[3]=z2; dst[4]=z2; } }

#define APPLY(v, HOP) { \
    aI  = HOP(aI,  v[0]); aJ  = HOP(aJ,  v[1]); \
    aI2 = HOP(aI2, v[2]); aJ2 = HOP(aJ2, v[3]); \
    aIJ = HOP(aIJ, v[4]); }

#define CCEMIT { \
    float2 fI = __half22float2(aI),  fJ = __half22float2(aJ); \
    float2 fA = __half22float2(aI2), fB = __half22float2(aJ2); \
    float2 fC = __half22float2(aIJ); \
    acc += cc1(fI.x, fJ.x, fA.x, fB.x, fC.x); \
    acc += cc1(fI.y, fJ.y, fA.y, fB.y, fC.y); }

    // prologue: window for plane d0 (taps d0-4 .. d0+4)
#pragma unroll
    for (int t = -4; t <= 4; t++) {
        int dt = d0 + t;                          // d0+4 <= 148 < 160 always
        if (dt >= 0) {
            __half2 v[5];
            LOADTAP(v, true, dt);
            APPLY(v, __hadd2);
        }
    }

    float acc = 0.f;
#pragma unroll 2
    for (int dd = 0; dd < 16; dd += 2) {
        const int d = d0 + dd;
        __half2 va[5], vs[5], wa[5], ws[5];
        LOADTAP(va, (d + 5) < DD, d + 5);
        LOADTAP(vs, (d - 4) >= 0, d - 4);
        LOADTAP(wa, (d + 6) < DD, d + 6);
        LOADTAP(ws, (d - 3) >= 0, d - 3);
        CCEMIT;                       // plane d
        APPLY(va, __hadd2);
        APPLY(vs, __hsub2);
        CCEMIT;                       // plane d+1
        APPLY(wa, __hadd2);
        APPLY(ws, __hsub2);
    }
#undef LOADTAP
#undef APPLY
#undef CCEMIT

    // block reduction
#pragma unroll
    for (int o = 16; o > 0; o >>= 1) acc += __shfl_xor_sync(0xFFFFFFFFu, acc, o);
    __shared__ float wsum[8];
    if ((tid & 31) == 0) wsum[tid >> 5] = acc;
    __syncthreads();
    if (tid == 0) {
        float s = 0.f;
#pragma unroll
        for (int i = 0; i < 8; i++) s += wsum[i];
        atomicAdd(out, -s * (1.0f / (float)VV));
    }
}

// ---------------------------------------------------------------------------
extern "C" void kernel_launch(void* const* d_in, const int* in_sizes, int n_in,
                              void* d_out, int out_size) {
    const float* I = (const float*)d_in[0];
    const float* J = (const float*)d_in[1];
    float* out = (float*)d_out;

    whpass<<<dim3(4, 6, DD), 256>>>(I, J, out);  // 4 W x 6 H x 160 d
    dpass<<<dim3(84, 10), 256>>>(out);           // 21504 h2-cols / 256, 10 D-chunks
}

// round 14
// speedup vs baseline: 1.2445x; 1.0134x over previous
#include <cuda_runtime.h>
#include <cuda_fp16.h>

#define DD 160
#define HH 192
#define WW 224
#define VV (DD*HH*WW)        // 6881280
#define W4 (WW/4)            // 56 float4 per input row
#define WU2 (WW/4)           // 56 uint2 (4-half) per row
#define VU2 (VV/4)           // uint2 elems per field = 1720320
#define PL2 (HH*WW/4)        // uint2 per d-plane = 10752

#define WC 56                // W outputs per block
#define HC 32                // H outputs per block
#define RH 40                // raw rows (HC + 8)
#define RST 68               // raw smem stride (uints = half2 voxels)
#define SST 15               // summed smem stride (uint2 per row)

#define DCHUNK 10            // dpass D outputs per block -> 16 chunks, 672 blocks

// fp16 scratch: 5 fields x VV halves (68.8 MB) — WH-summed fields
__device__ __half g_B[5u * VV];

union U2H4 { uint2 u; __half2 h[2]; };
union U4H2 { uint4 u; __half2 h[4]; };

// ---------------------------------------------------------------------------
// Fused pass 1+2 (CHAMPION, unchanged): W-sum then H-sum, fp32 in, fp16 out.
// Raw tile held as packed half2(I,J) -> 34.9 KB smem -> 6 blocks/SM.
// ---------------------------------------------------------------------------
__global__ void __launch_bounds__(256) whpass(const float* __restrict__ I,
                                              const float* __restrict__ J,
                                              float* __restrict__ out) {
    __shared__ __align__(16) unsigned sR[RH * RST];  // 10.9 KB: half2(I,J)/voxel
    __shared__ __align__(16) uint2 sS[5 * RH * SST]; // 24 KB

    const int tid = threadIdx.x;
    const int w0  = blockIdx.x * WC;
    const int h0  = blockIdx.y * HC;
    const int d   = blockIdx.z;
    if (blockIdx.x == 0 && blockIdx.y == 0 && blockIdx.z == 0 && tid == 0)
        out[0] = 0.f;

    // ---- phase 0: load raw I,J tile rows [h0-4, h0+36), w [w0-4, w0+60) ----
    const int fb = (w0 - 4) >> 2;           // first float4 index (may be -1)
    const float4* I4 = (const float4*)I;
    const float4* J4 = (const float4*)J;
    for (int i = tid; i < RH * 16; i += 256) {
        const int r = i >> 4, c = i & 15;
        const int gh = h0 - 4 + r;
        const int gf = fb + c;
        float4 a = make_float4(0.f, 0.f, 0.f, 0.f);
        float4 b = a;
        if (gh >= 0 && gh < HH && gf >= 0 && gf < W4) {
            const size_t q = ((size_t)d * HH + gh) * W4 + gf;
            a = I4[q]; b = J4[q];
        }
        U4H2 t;
        t.h[0] = __floats2half2_rn(a.x, b.x);
        t.h[1] = __floats2half2_rn(a.y, b.y);
        t.h[2] = __floats2half2_rn(a.z, b.z);
        t.h[3] = __floats2half2_rn(a.w, b.w);
        *(uint4*)&sR[r * RST + 4 * c] = t.u;    // 16B aligned
    }
    __syncthreads();

    // ---- phase 1: W-sums (sliding 9-tap), 4 outputs/item, 5 fields -> sS ----
    for (int i = tid; i < 14 * RH; i += 256) {
        const int g = i / RH;              // output float4-group 0..13
        const int r = i - g * RH;          // row 0..39 (consecutive tids -> r)
        const int base = r * RST + 4 * g;  // 16B aligned

        float iv[12], jv[12];
        U4H2 q0, q1, q2;
        q0.u = *(const uint4*)&sR[base];
        q1.u = *(const uint4*)&sR[base + 4];
        q2.u = *(const uint4*)&sR[base + 8];
#pragma unroll
        for (int t = 0; t < 4; t++) {
            float2 v0 = __half22float2(q0.h[t]);
            float2 v1 = __half22float2(q1.h[t]);
            float2 v2 = __half22float2(q2.h[t]);
            iv[t] = v0.x;     jv[t] = v0.y;
            iv[t + 4] = v1.x; jv[t + 4] = v1.y;
            iv[t + 8] = v2.x; jv[t + 8] = v2.y;
        }

        float oi[4], oj[4], oi2[4], oj2[4], oij[4];
        float si=0.f, sj=0.f, si2=0.f, sj2=0.f, sij=0.f;
#pragma unroll
        for (int t = 0; t < 9; t++) {
            float x = iv[t], y = jv[t];
            si += x; sj += y; si2 += x*x; sj2 += y*y; sij += x*y;
        }
        oi[0]=si; oj[0]=sj; oi2[0]=si2; oj2[0]=sj2; oij[0]=sij;
#pragma unroll
        for (int k = 1; k < 4; k++) {
            float ia = iv[k+8], ir = iv[k-1];
            float ja = jv[k+8], jr = jv[k-1];
            si  += ia - ir;        sj  += ja - jr;
            si2 += ia*ia - ir*ir;  sj2 += ja*ja - jr*jr;
            sij += ia*ja - ir*jr;
            oi[k]=si; oj[k]=sj; oi2[k]=si2; oj2[k]=sj2; oij[k]=sij;
        }

        const int so = r * SST + g;
        U2H4 t0, t1, t2, t3, t4;
        t0.h[0]=__floats2half2_rn(oi[0],oi[1]);   t0.h[1]=__floats2half2_rn(oi[2],oi[3]);
        t1.h[0]=__floats2half2_rn(oj[0],oj[1]);   t1.h[1]=__floats2half2_rn(oj[2],oj[3]);
        t2.h[0]=__floats2half2_rn(oi2[0],oi2[1]); t2.h[1]=__floats2half2_rn(oi2[2],oi2[3]);
        t3.h[0]=__floats2half2_rn(oj2[0],oj2[1]); t3.h[1]=__floats2half2_rn(oj2[2],oj2[3]);
        t4.h[0]=__floats2half2_rn(oij[0],oij[1]); t4.h[1]=__floats2half2_rn(oij[2],oij[3]);
        sS[0*RH*SST + so] = t0.u;
        sS[1*RH*SST + so] = t1.u;
        sS[2*RH*SST + so] = t2.u;
        sS[3*RH*SST + so] = t3.u;
        sS[4*RH*SST + so] = t4.u;
    }
    __syncthreads();

    // ---- phase 2: H-sums (running window over sS rows) -> g_B --------------
    if (tid < 224) {
        const int col  = tid % 14;          // uint2 column in tile
        const int rest = tid / 14;          // 0..15
        const int seg  = rest & 7;          // 4-row segment
        const int grp  = rest >> 3;         // 0: fields 0-2, 1: fields 3-4
        const int f0 = grp ? 3 : 0;
        const int f1 = grp ? 5 : 3;
        const int o0 = seg * 4;             // local output row base

        uint2* Bg = (uint2*)g_B;
        for (int f = f0; f < f1; f++) {
            const uint2* sf = &sS[f * RH * SST];
            __half2 s0 = __float2half2_rn(0.f), s1 = s0;
#pragma unroll
            for (int t = 0; t < 9; t++) {        // taps lr = o0 .. o0+8
                U2H4 v; v.u = sf[(o0 + t) * SST + col];
                s0 = __hadd2(s0, v.h[0]); s1 = __hadd2(s1, v.h[1]);
            }
            const size_t fbase = (size_t)f * VU2 + blockIdx.x * 14 + col;
#pragma unroll
            for (int k = 0; k < 4; k++) {
                U2H4 o; o.h[0] = s0; o.h[1] = s1;
                Bg[fbase + ((size_t)d * HH + h0 + o0 + k) * WU2] = o.u;
                if (k < 3) {
                    U2H4 va, vs;
                    va.u = sf[(o0 + k + 9) * SST + col];
                    vs.u = sf[(o0 + k) * SST + col];
                    s0 = __hadd2(__hsub2(s0, vs.h[0]), va.h[0]);
                    s1 = __hadd2(__hsub2(s1, vs.h[1]), va.h[1]);
                }
            }
        }
    }
}

// ---------------------------------------------------------------------------
// Pass 3: along D. uint2 threads, chunk 10, 2-plane batched loads
// (20 LDG.64 in flight). 672 blocks = 4.5/SM resident. NO reg cap (no spills).
// ---------------------------------------------------------------------------
__device__ __forceinline__ float cc1(float si, float sj, float si2, float sj2, float sij) {
    const float inv = 1.0f / 729.0f;
    float cross = sij - si * sj * inv;
    float ivar  = si2 - si * si * inv;
    float jvar  = sj2 - sj * sj * inv;
    return __fdividef(cross * cross, ivar * jvar + 1e-5f);
}

__global__ void __launch_bounds__(256) dpass(float* __restrict__ out) {
    const int tid = threadIdx.x;
    const int col = blockIdx.x * 256 + tid;      // uint2 index within plane
    const int d0  = blockIdx.y * DCHUNK;
    const uint2* B = (const uint2*)g_B;

    __half2 z2 = __float2half2_rn(0.f);
    __half2 aI0=z2, aI1=z2, aJ0=z2, aJ1=z2, aI20=z2, aI21=z2,
            aJ20=z2, aJ21=z2, aIJ0=z2, aIJ1=z2;

#define LOADTAP(dst, cond, dp) { \
    if (cond) { const unsigned q_ = (unsigned)(dp) * PL2 + col; \
        dst[0].u = B[0u*VU2 + q_]; dst[1].u = B[1u*VU2 + q_]; \
        dst[2].u = B[2u*VU2 + q_]; dst[3].u = B[3u*VU2 + q_]; \
        dst[4].u = B[4u*VU2 + q_]; } \
    else { uint2 z = make_uint2(0u, 0u); \
        dst[0].u = z; dst[1].u = z; dst[2].u = z; dst[3].u = z; dst[4].u = z; } }

#define APPLY(v, HOP) { \
    aI0  = HOP(aI0,  v[0].h[0]); aI1  = HOP(aI1,  v[0].h[1]); \
    aJ0  = HOP(aJ0,  v[1].h[0]); aJ1  = HOP(aJ1,  v[1].h[1]); \
    aI20 = HOP(aI20, v[2].h[0]); aI21 = HOP(aI21, v[2].h[1]); \
    aJ20 = HOP(aJ20, v[3].h[0]); aJ21 = HOP(aJ21, v[3].h[1]); \
    aIJ0 = HOP(aIJ0, v[4].h[0]); aIJ1 = HOP(aIJ1, v[4].h[1]); }

#define CCEMIT { \
    float2 fI0=__half22float2(aI0),  fI1=__half22float2(aI1); \
    float2 fJ0=__half22float2(aJ0),  fJ1=__half22float2(aJ1); \
    float2 fA0=__half22float2(aI20), fA1=__half22float2(aI21); \
    float2 fB0=__half22float2(aJ20), fB1=__half22float2(aJ21); \
    float2 fC0=__half22float2(aIJ0), fC1=__half22float2(aIJ1); \
    acc += cc1(fI0.x, fJ0.x, fA0.x, fB0.x, fC0.x); \
    acc += cc1(fI0.y, fJ0.y, fA0.y, fB0.y, fC0.y); \
    acc += cc1(fI1.x, fJ1.x, fA1.x, fB1.x, fC1.x); \
    acc += cc1(fI1.y, fJ1.y, fA1.y, fB1.y, fC1.y); }

    // prologue: window for plane d0 (taps d0-4 .. d0+4)
#pragma unroll
    for (int t = -4; t <= 4; t++) {
        int dt = d0 + t;                          // d0+4 <= 154 < 160 always
        if (dt >= 0) {
            U2H4 v[5];
            LOADTAP(v, true, dt);
            APPLY(v, __hadd2);
        }
    }

    float acc = 0.f;
#pragma unroll 5
    for (int dd = 0; dd < DCHUNK; dd += 2) {
        const int d = d0 + dd;
        U2H4 va[5], vs[5], wa[5], ws[5];
        LOADTAP(va, (d + 5) < DD, d + 5);
        LOADTAP(vs, (d - 4) >= 0, d - 4);
        LOADTAP(wa, (d + 6) < DD, d + 6);
        LOADTAP(ws, (d - 3) >= 0, d - 3);
        CCEMIT;                       // plane d
        APPLY(va, __hadd2);
        APPLY(vs, __hsub2);
        CCEMIT;                       // plane d+1
        APPLY(wa, __hadd2);
        APPLY(ws, __hsub2);
    }
#undef LOADTAP
#undef APPLY
#undef CCEMIT

    // block reduction
#pragma unroll
    for (int o = 16; o > 0; o >>= 1) acc += __shfl_xor_sync(0xFFFFFFFFu, acc, o);
    __shared__ float wsum[8];
    if ((tid & 31) == 0) wsum[tid >> 5] = acc;
    __syncthreads();
    if (tid == 0) {
        float s = 0.f;
#pragma unroll
        for (int i = 0; i < 8; i++) s += wsum[i];
        atomicAdd(out, -s * (1.0f / (float)VV));
    }
}

// ---------------------------------------------------------------------------
extern "C" void kernel_launch(void* const* d_in, const int* in_sizes, int n_in,
                              void* d_out, int out_size) {
    const float* I = (const float*)d_in[0];
    const float* J = (const float*)d_in[1];
    float* out = (float*)d_out;

    whpass<<<dim3(4, 6, DD), 256>>>(I, J, out);  // 4 W x 6 H x 160 d
    dpass<<<dim3(42, 16), 256>>>(out);           // 10752 u2-cols / 256, 16 D-chunks
}

// round 15
// speedup vs baseline: 1.2695x; 1.0201x over previous
#include <cuda_runtime.h>
#include <cuda_fp16.h>

#define DD 160
#define HH 192
#define WW 224
#define VV (DD*HH*WW)        // 6881280
#define W4 (WW/4)            // 56 float4 per input row
#define WU2 (WW/4)           // 56 uint2 (4-half) per row
#define VU2 (VV/4)           // uint2 elems per field = 1720320
#define PL2 (HH*WW/4)        // uint2 per d-plane = 10752

#define WC 56                // W outputs per block
#define HC 32                // H outputs per block
#define RH 40                // raw rows (HC + 8)
#define RST 68               // raw smem stride (uints = half2 voxels)
#define SST 15               // summed smem stride (uint2 per row)

#define DCHUNK 12            // dpass D outputs per block -> 14 chunks, 588 blocks
                             // 588 <= 592 (148 SM x 4 blocks) -> ONE full wave

// fp16 scratch: 5 fields x VV halves (68.8 MB) — WH-summed fields
__device__ __half g_B[5u * VV];

union U2H4 { uint2 u; __half2 h[2]; };
union U4H2 { uint4 u; __half2 h[4]; };

// ---------------------------------------------------------------------------
// Fused pass 1+2 (CHAMPION, unchanged): W-sum then H-sum, fp32 in, fp16 out.
// Raw tile held as packed half2(I,J) -> 34.9 KB smem -> 6 blocks/SM.
// ---------------------------------------------------------------------------
__global__ void __launch_bounds__(256) whpass(const float* __restrict__ I,
                                              const float* __restrict__ J,
                                              float* __restrict__ out) {
    __shared__ __align__(16) unsigned sR[RH * RST];  // 10.9 KB: half2(I,J)/voxel
    __shared__ __align__(16) uint2 sS[5 * RH * SST]; // 24 KB

    const int tid = threadIdx.x;
    const int w0  = blockIdx.x * WC;
    const int h0  = blockIdx.y * HC;
    const int d   = blockIdx.z;
    if (blockIdx.x == 0 && blockIdx.y == 0 && blockIdx.z == 0 && tid == 0)
        out[0] = 0.f;

    // ---- phase 0: load raw I,J tile rows [h0-4, h0+36), w [w0-4, w0+60) ----
    const int fb = (w0 - 4) >> 2;           // first float4 index (may be -1)
    const float4* I4 = (const float4*)I;
    const float4* J4 = (const float4*)J;
    for (int i = tid; i < RH * 16; i += 256) {
        const int r = i >> 4, c = i & 15;
        const int gh = h0 - 4 + r;
        const int gf = fb + c;
        float4 a = make_float4(0.f, 0.f, 0.f, 0.f);
        float4 b = a;
        if (gh >= 0 && gh < HH && gf >= 0 && gf < W4) {
            const size_t q = ((size_t)d * HH + gh) * W4 + gf;
            a = I4[q]; b = J4[q];
        }
        U4H2 t;
        t.h[0] = __floats2half2_rn(a.x, b.x);
        t.h[1] = __floats2half2_rn(a.y, b.y);
        t.h[2] = __floats2half2_rn(a.z, b.z);
        t.h[3] = __floats2half2_rn(a.w, b.w);
        *(uint4*)&sR[r * RST + 4 * c] = t.u;    // 16B aligned
    }
    __syncthreads();

    // ---- phase 1: W-sums (sliding 9-tap), 4 outputs/item, 5 fields -> sS ----
    for (int i = tid; i < 14 * RH; i += 256) {
        const int g = i / RH;              // output float4-group 0..13
        const int r = i - g * RH;          // row 0..39 (consecutive tids -> r)
        const int base = r * RST + 4 * g;  // 16B aligned

        float iv[12], jv[12];
        U4H2 q0, q1, q2;
        q0.u = *(const uint4*)&sR[base];
        q1.u = *(const uint4*)&sR[base + 4];
        q2.u = *(const uint4*)&sR[base + 8];
#pragma unroll
        for (int t = 0; t < 4; t++) {
            float2 v0 = __half22float2(q0.h[t]);
            float2 v1 = __half22float2(q1.h[t]);
            float2 v2 = __half22float2(q2.h[t]);
            iv[t] = v0.x;     jv[t] = v0.y;
            iv[t + 4] = v1.x; jv[t + 4] = v1.y;
            iv[t + 8] = v2.x; jv[t + 8] = v2.y;
        }

        float oi[4], oj[4], oi2[4], oj2[4], oij[4];
        float si=0.f, sj=0.f, si2=0.f, sj2=0.f, sij=0.f;
#pragma unroll
        for (int t = 0; t < 9; t++) {
            float x = iv[t], y = jv[t];
            si += x; sj += y; si2 += x*x; sj2 += y*y; sij += x*y;
        }
        oi[0]=si; oj[0]=sj; oi2[0]=si2; oj2[0]=sj2; oij[0]=sij;
#pragma unroll
        for (int k = 1; k < 4; k++) {
            float ia = iv[k+8], ir = iv[k-1];
            float ja = jv[k+8], jr = jv[k-1];
            si  += ia - ir;        sj  += ja - jr;
            si2 += ia*ia - ir*ir;  sj2 += ja*ja - jr*jr;
            sij += ia*ja - ir*jr;
            oi[k]=si; oj[k]=sj; oi2[k]=si2; oj2[k]=sj2; oij[k]=sij;
        }

        const int so = r * SST + g;
        U2H4 t0, t1, t2, t3, t4;
        t0.h[0]=__floats2half2_rn(oi[0],oi[1]);   t0.h[1]=__floats2half2_rn(oi[2],oi[3]);
        t1.h[0]=__floats2half2_rn(oj[0],oj[1]);   t1.h[1]=__floats2half2_rn(oj[2],oj[3]);
        t2.h[0]=__floats2half2_rn(oi2[0],oi2[1]); t2.h[1]=__floats2half2_rn(oi2[2],oi2[3]);
        t3.h[0]=__floats2half2_rn(oj2[0],oj2[1]); t3.h[1]=__floats2half2_rn(oj2[2],oj2[3]);
        t4.h[0]=__floats2half2_rn(oij[0],oij[1]); t4.h[1]=__floats2half2_rn(oij[2],oij[3]);
        sS[0*RH*SST + so] = t0.u;
        sS[1*RH*SST + so] = t1.u;
        sS[2*RH*SST + so] = t2.u;
        sS[3*RH*SST + so] = t3.u;
        sS[4*RH*SST + so] = t4.u;
    }
    __syncthreads();

    // ---- phase 2: H-sums (running window over sS rows) -> g_B --------------
    if (tid < 224) {
        const int col  = tid % 14;          // uint2 column in tile
        const int rest = tid / 14;          // 0..15
        const int seg  = rest & 7;          // 4-row segment
        const int grp  = rest >> 3;         // 0: fields 0-2, 1: fields 3-4
        const int f0 = grp ? 3 : 0;
        const int f1 = grp ? 5 : 3;
        const int o0 = seg * 4;             // local output row base

        uint2* Bg = (uint2*)g_B;
        for (int f = f0; f < f1; f++) {
            const uint2* sf = &sS[f * RH * SST];
            __half2 s0 = __float2half2_rn(0.f), s1 = s0;
#pragma unroll
            for (int t = 0; t < 9; t++) {        // taps lr = o0 .. o0+8
                U2H4 v; v.u = sf[(o0 + t) * SST + col];
                s0 = __hadd2(s0, v.h[0]); s1 = __hadd2(s1, v.h[1]);
            }
            const size_t fbase = (size_t)f * VU2 + blockIdx.x * 14 + col;
#pragma unroll
            for (int k = 0; k < 4; k++) {
                U2H4 o; o.h[0] = s0; o.h[1] = s1;
                Bg[fbase + ((size_t)d * HH + h0 + o0 + k) * WU2] = o.u;
                if (k < 3) {
                    U2H4 va, vs;
                    va.u = sf[(o0 + k + 9) * SST + col];
                    vs.u = sf[(o0 + k) * SST + col];
                    s0 = __hadd2(__hsub2(s0, vs.h[0]), va.h[0]);
                    s1 = __hadd2(__hsub2(s1, vs.h[1]), va.h[1]);
                }
            }
        }
    }
}

// ---------------------------------------------------------------------------
// Pass 3: along D. uint2 threads, chunk 12, 2-plane batched loads
// (R10 codegen shape: #pragma unroll 2, no reg cap). 588 blocks = ONE wave.
// ---------------------------------------------------------------------------
__device__ __forceinline__ float cc1(float si, float sj, float si2, float sj2, float sij) {
    const float inv = 1.0f / 729.0f;
    float cross = sij - si * sj * inv;
    float ivar  = si2 - si * si * inv;
    float jvar  = sj2 - sj * sj * inv;
    return __fdividef(cross * cross, ivar * jvar + 1e-5f);
}

__global__ void __launch_bounds__(256) dpass(float* __restrict__ out) {
    const int tid = threadIdx.x;
    const int col = blockIdx.x * 256 + tid;      // uint2 index within plane
    const int d0  = blockIdx.y * DCHUNK;
    const uint2* B = (const uint2*)g_B;

    __half2 z2 = __float2half2_rn(0.f);
    __half2 aI0=z2, aI1=z2, aJ0=z2, aJ1=z2, aI20=z2, aI21=z2,
            aJ20=z2, aJ21=z2, aIJ0=z2, aIJ1=z2;

#define LOADTAP(dst, cond, dp) { \
    if (cond) { const unsigned q_ = (unsigned)(dp) * PL2 + col; \
        dst[0].u = B[0u*VU2 + q_]; dst[1].u = B[1u*VU2 + q_]; \
        dst[2].u = B[2u*VU2 + q_]; dst[3].u = B[3u*VU2 + q_]; \
        dst[4].u = B[4u*VU2 + q_]; } \
    else { uint2 z = make_uint2(0u, 0u); \
        dst[0].u = z; dst[1].u = z; dst[2].u = z; dst[3].u = z; dst[4].u = z; } }

#define APPLY(v, HOP) { \
    aI0  = HOP(aI0,  v[0].h[0]); aI1  = HOP(aI1,  v[0].h[1]); \
    aJ0  = HOP(aJ0,  v[1].h[0]); aJ1  = HOP(aJ1,  v[1].h[1]); \
    aI20 = HOP(aI20, v[2].h[0]); aI21 = HOP(aI21, v[2].h[1]); \
    aJ20 = HOP(aJ20, v[3].h[0]); aJ21 = HOP(aJ21, v[3].h[1]); \
    aIJ0 = HOP(aIJ0, v[4].h[0]); aIJ1 = HOP(aIJ1, v[4].h[1]); }

#define CCEMIT { \
    float2 fI0=__half22float2(aI0),  fI1=__half22float2(aI1); \
    float2 fJ0=__half22float2(aJ0),  fJ1=__half22float2(aJ1); \
    float2 fA0=__half22float2(aI20), fA1=__half22float2(aI21); \
    float2 fB0=__half22float2(aJ20), fB1=__half22float2(aJ21); \
    float2 fC0=__half22float2(aIJ0), fC1=__half22float2(aIJ1); \
    acc += cc1(fI0.x, fJ0.x, fA0.x, fB0.x, fC0.x); \
    acc += cc1(fI0.y, fJ0.y, fA0.y, fB0.y, fC0.y); \
    acc += cc1(fI1.x, fJ1.x, fA1.x, fB1.x, fC1.x); \
    acc += cc1(fI1.y, fJ1.y, fA1.y, fB1.y, fC1.y); }

    // prologue: window for plane d0 (taps d0-4 .. d0+4; d0 max = 156)
#pragma unroll
    for (int t = -4; t <= 4; t++) {
        int dt = d0 + t;
        if (dt >= 0 && dt < DD) {
            U2H4 v[5];
            LOADTAP(v, true, dt);
            APPLY(v, __hadd2);
        }
    }

    float acc = 0.f;
#pragma unroll 2
    for (int dd = 0; dd < DCHUNK; dd += 2) {
        const int d = d0 + dd;
        U2H4 va[5], vs[5], wa[5], ws[5];
        LOADTAP(va, (d + 5) < DD, d + 5);
        LOADTAP(vs, (d - 4) >= 0, d - 4);
        LOADTAP(wa, (d + 6) < DD, d + 6);
        LOADTAP(ws, (d - 3) >= 0, d - 3);
        if (d < DD)     CCEMIT;       // plane d
        APPLY(va, __hadd2);
        APPLY(vs, __hsub2);
        if (d + 1 < DD) CCEMIT;       // plane d+1
        APPLY(wa, __hadd2);
        APPLY(ws, __hsub2);
    }
#undef LOADTAP
#undef APPLY
#undef CCEMIT

    // block reduction
#pragma unroll
    for (int o = 16; o > 0; o >>= 1) acc += __shfl_xor_sync(0xFFFFFFFFu, acc, o);
    __shared__ float wsum[8];
    if ((tid & 31) == 0) wsum[tid >> 5] = acc;
    __syncthreads();
    if (tid == 0) {
        float s = 0.f;
#pragma unroll
        for (int i = 0; i < 8; i++) s += wsum[i];
        atomicAdd(out, -s * (1.0f / (float)VV));
    }
}

// ---------------------------------------------------------------------------
extern "C" void kernel_launch(void* const* d_in, const int* in_sizes, int n_in,
                              void* d_out, int out_size) {
    const float* I = (const float*)d_in[0];
    const float* J = (const float*)d_in[1];
    float* out = (float*)d_out;

    whpass<<<dim3(4, 6, DD), 256>>>(I, J, out);  // 4 W x 6 H x 160 d
    dpass<<<dim3(42, 14), 256>>>(out);           // 10752 u2-cols / 256, 14 D-chunks
}